// round 1
// baseline (speedup 1.0000x reference)
#include <cuda_runtime.h>
#include <math.h>

// ---------------------------------------------------------------------------
// PromptWindowAttention: Swin window attention with 5 prompt tokens.
//   x:        (1024, 54, 384) f32
//   mask:     (64, 49, 49)    f32
//   qkv_w:    (1152, 384)     f32   qkv = x @ qkv_w^T + qkv_b
//   qkv_b:    (1152,)
//   proj_w:   (384, 384)      f32   out = y @ proj_w^T + proj_b
//   proj_b:   (384,)
//   rpb_table:(169, 12)       f32
//   out:      (1024, 54, 384) f32
// ---------------------------------------------------------------------------

#define DIMC   384
#define NH     12
#define HD     32
#define NTOK   54
#define WINSZ  49
#define NP     5
#define BATCH  1024
#define MROWS  (BATCH * NTOK)      // 55296
#define QKVC   (3 * DIMC)          // 1152

// Scratch (allocation-free rule: __device__ globals)
__device__ float g_qkv[(size_t)MROWS * QKVC];   // 255 MB
__device__ float g_att[(size_t)MROWS * DIMC];   //  85 MB

// ---------------------------------------------------------------------------
// GEMM (TN form): C[m,n] = sum_k A[m,k] * B[n,k] + bias[n]
// A: (M,K) row-major, B: (N,K) row-major. M%128==0, N%128==0, K%16==0.
// 128x128 block tile, 16-deep K step, 256 threads, 8x8 microtile.
// ---------------------------------------------------------------------------
__global__ __launch_bounds__(256, 2)
void gemm_tn_bias(const float* __restrict__ A, const float* __restrict__ B,
                  const float* __restrict__ bias, float* __restrict__ C,
                  int M, int N, int K) {
    constexpr int BM = 128, BN = 128, BK = 16;
    __shared__ float As[BK][BM];
    __shared__ float Bs[BK][BN];

    const int tid = threadIdx.x;          // 0..255
    const int tm  = tid >> 4;             // 0..15
    const int tn  = tid & 15;             // 0..15
    const int m0  = blockIdx.x * BM;
    const int n0  = blockIdx.y * BN;

    const int lr = tid >> 2;              // 0..63 (row within 64-row slab)
    const int lk = (tid & 3) << 2;        // 0,4,8,12 (k offset, float4)

    float acc[8][8];
#pragma unroll
    for (int i = 0; i < 8; i++)
#pragma unroll
        for (int j = 0; j < 8; j++) acc[i][j] = 0.f;

    for (int k0 = 0; k0 < K; k0 += BK) {
        // Load A tile (128 rows x 16 k), transposed into As[k][m]
#pragma unroll
        for (int r = 0; r < BM; r += 64) {
            const float4 v = *reinterpret_cast<const float4*>(
                &A[(size_t)(m0 + r + lr) * K + k0 + lk]);
            As[lk + 0][r + lr] = v.x;
            As[lk + 1][r + lr] = v.y;
            As[lk + 2][r + lr] = v.z;
            As[lk + 3][r + lr] = v.w;
        }
        // Load B tile (128 n-rows x 16 k), transposed into Bs[k][n]
#pragma unroll
        for (int r = 0; r < BN; r += 64) {
            const float4 v = *reinterpret_cast<const float4*>(
                &B[(size_t)(n0 + r + lr) * K + k0 + lk]);
            Bs[lk + 0][r + lr] = v.x;
            Bs[lk + 1][r + lr] = v.y;
            Bs[lk + 2][r + lr] = v.z;
            Bs[lk + 3][r + lr] = v.w;
        }
        __syncthreads();

#pragma unroll
        for (int kk = 0; kk < BK; kk++) {
            float a[8], b[8];
            const float4 a0 = *reinterpret_cast<const float4*>(&As[kk][tm * 8]);
            const float4 a1 = *reinterpret_cast<const float4*>(&As[kk][tm * 8 + 4]);
            const float4 b0 = *reinterpret_cast<const float4*>(&Bs[kk][tn * 8]);
            const float4 b1 = *reinterpret_cast<const float4*>(&Bs[kk][tn * 8 + 4]);
            a[0]=a0.x; a[1]=a0.y; a[2]=a0.z; a[3]=a0.w;
            a[4]=a1.x; a[5]=a1.y; a[6]=a1.z; a[7]=a1.w;
            b[0]=b0.x; b[1]=b0.y; b[2]=b0.z; b[3]=b0.w;
            b[4]=b1.x; b[5]=b1.y; b[6]=b1.z; b[7]=b1.w;
#pragma unroll
            for (int i = 0; i < 8; i++)
#pragma unroll
                for (int j = 0; j < 8; j++)
                    acc[i][j] = fmaf(a[i], b[j], acc[i][j]);
        }
        __syncthreads();
    }

    // Epilogue: add bias, vectorized store
    float bb[8];
#pragma unroll
    for (int j = 0; j < 8; j++) bb[j] = bias[n0 + tn * 8 + j];

#pragma unroll
    for (int i = 0; i < 8; i++) {
        const int row = m0 + tm * 8 + i;
        float4 o0, o1;
        o0.x = acc[i][0] + bb[0]; o0.y = acc[i][1] + bb[1];
        o0.z = acc[i][2] + bb[2]; o0.w = acc[i][3] + bb[3];
        o1.x = acc[i][4] + bb[4]; o1.y = acc[i][5] + bb[5];
        o1.z = acc[i][6] + bb[6]; o1.w = acc[i][7] + bb[7];
        *reinterpret_cast<float4*>(&C[(size_t)row * N + n0 + tn * 8])     = o0;
        *reinterpret_cast<float4*>(&C[(size_t)row * N + n0 + tn * 8 + 4]) = o1;
    }
}

// ---------------------------------------------------------------------------
// Attention per (b, h): logits + rel-pos-bias + window-mask + softmax + PV
// grid (1024, 12), 128 threads. Reads g_qkv, writes g_att.
// ---------------------------------------------------------------------------
__global__ __launch_bounds__(128)
void attn_kernel(const float* __restrict__ mask,
                 const float* __restrict__ rpb) {
    const int b = blockIdx.x;
    const int h = blockIdx.y;
    const int tid = threadIdx.x;

    __shared__ float qs[NTOK][HD + 1];
    __shared__ float ks[NTOK][HD + 1];
    __shared__ float vs[NTOK][HD + 1];
    __shared__ float at[NTOK][NTOK + 2];

    const float scale = 0.17677669529663687f;   // 32^-0.5
    const size_t base = (size_t)b * NTOK * QKVC + (size_t)h * HD;

    for (int idx = tid; idx < NTOK * HD; idx += 128) {
        const int n = idx >> 5, d = idx & 31;
        const size_t r = base + (size_t)n * QKVC + d;
        qs[n][d] = g_qkv[r] * scale;
        ks[n][d] = g_qkv[r + DIMC];
        vs[n][d] = g_qkv[r + 2 * DIMC];
    }
    __syncthreads();

    const int w = b & 63;   // window index = b % 64
    for (int p = tid; p < NTOK * NTOK; p += 128) {
        const int i = p / NTOK;
        const int j = p - i * NTOK;
        float s = 0.f;
#pragma unroll
        for (int d = 0; d < HD; d++) s = fmaf(qs[i][d], ks[j][d], s);
        if (i >= NP && j >= NP) {
            const int pi = i - NP, pj = j - NP;
            const int r1 = pi / 7, c1 = pi - r1 * 7;
            const int r2 = pj / 7, c2 = pj - r2 * 7;
            const int ridx = (r1 - r2 + 6) * 13 + (c1 - c2 + 6);
            s += rpb[ridx * NH + h] + mask[((size_t)w * WINSZ + pi) * WINSZ + pj];
        }
        at[i][j] = s;
    }
    __syncthreads();

    // Row softmax (54 rows, one thread each; tiny work)
    if (tid < NTOK) {
        float mx = -1e30f;
#pragma unroll
        for (int j = 0; j < NTOK; j++) mx = fmaxf(mx, at[tid][j]);
        float sum = 0.f;
#pragma unroll
        for (int j = 0; j < NTOK; j++) {
            const float e = __expf(at[tid][j] - mx);
            at[tid][j] = e;
            sum += e;
        }
        const float inv = 1.f / sum;
#pragma unroll
        for (int j = 0; j < NTOK; j++) at[tid][j] *= inv;
    }
    __syncthreads();

    // out[i,d] = sum_j attn[i,j] * v[j,d]
    for (int idx = tid; idx < NTOK * HD; idx += 128) {
        const int i = idx >> 5, d = idx & 31;
        float s = 0.f;
#pragma unroll
        for (int j = 0; j < NTOK; j++) s = fmaf(at[i][j], vs[j][d], s);
        g_att[((size_t)b * NTOK + i) * DIMC + (size_t)h * HD + d] = s;
    }
}

// ---------------------------------------------------------------------------
extern "C" void kernel_launch(void* const* d_in, const int* in_sizes, int n_in,
                              void* d_out, int out_size) {
    const float* x      = (const float*)d_in[0];
    const float* mask   = (const float*)d_in[1];
    const float* qkv_w  = (const float*)d_in[2];
    const float* qkv_b  = (const float*)d_in[3];
    const float* proj_w = (const float*)d_in[4];
    const float* proj_b = (const float*)d_in[5];
    const float* rpb    = (const float*)d_in[6];
    float* out = (float*)d_out;

    float* qkvbuf = nullptr;
    float* attbuf = nullptr;
    cudaGetSymbolAddress((void**)&qkvbuf, g_qkv);
    cudaGetSymbolAddress((void**)&attbuf, g_att);

    // 1) QKV GEMM: (55296,384) x (1152,384)^T -> (55296,1152)
    {
        dim3 grid(MROWS / 128, QKVC / 128);   // (432, 9)
        gemm_tn_bias<<<grid, 256>>>(x, qkv_w, qkv_b, qkvbuf, MROWS, QKVC, DIMC);
    }
    // 2) Attention per (b, h)
    {
        dim3 grid(BATCH, NH);
        attn_kernel<<<grid, 128>>>(mask, rpb);
    }
    // 3) Proj GEMM: (55296,384) x (384,384)^T -> (55296,384)
    {
        dim3 grid(MROWS / 128, DIMC / 128);   // (432, 3)
        gemm_tn_bias<<<grid, 256>>>(attbuf, proj_w, proj_b, out, MROWS, DIMC, DIMC);
    }
}

// round 3
// speedup vs baseline: 2.6344x; 2.6344x over previous
#include <cuda_runtime.h>
#include <cstdint>
#include <math.h>

// ---------------------------------------------------------------------------
// PromptWindowAttention, sm_100-compatible tensor path (mma.sync tf32).
//   x:(1024,54,384)f32  mask:(64,49,49)  qkv_w:(1152,384)  qkv_b:(1152)
//   proj_w:(384,384)  proj_b:(384)  rpb:(169,12)  out:(1024,54,384)f32
// ---------------------------------------------------------------------------

#define DIMC   384
#define NH     12
#define HD     32
#define NTOK   54
#define WINSZ  49
#define NP     5
#define BATCH  1024
#define MROWS  (BATCH * NTOK)      // 55296
#define QKVC   (3 * DIMC)          // 1152
#define KDEPTH 384
#define NSTG   (KDEPTH / 32)       // 12

// Scratch (__device__ globals; allocation-free rule)
__device__ float g_xr [(size_t)MROWS * DIMC];   // tf32-rounded x        (85 MB)
__device__ float g_wr [(size_t)QKVC * DIMC];    // tf32-rounded qkv_w
__device__ float g_wr2[(size_t)DIMC * DIMC];    // tf32-rounded proj_w
__device__ float g_qkv[(size_t)MROWS * QKVC];   // qkv result f32       (255 MB)
__device__ float g_att[(size_t)MROWS * DIMC];   // attn out (tf32-rounded, 85 MB)

// ------------------------------ helpers ------------------------------------
__device__ __forceinline__ uint32_t smem_u32(const void* p) {
    uint32_t a;
    asm("{ .reg .u64 t; cvta.to.shared.u64 t, %1; cvt.u32.u64 %0, t; }" : "=r"(a) : "l"(p));
    return a;
}
__device__ __forceinline__ float round_tf32v(float v) {
    uint32_t r;
    asm("cvt.rna.tf32.f32 %0, %1;" : "=r"(r) : "f"(v));
    return __uint_as_float(r);
}
#define CP_ASYNC16(dst, src) \
    asm volatile("cp.async.cg.shared.global [%0], [%1], 16;" :: "r"(dst), "l"(src) : "memory")
#define CP_COMMIT() asm volatile("cp.async.commit_group;" ::: "memory")
#define CP_WAIT1()  asm volatile("cp.async.wait_group 1;" ::: "memory")
#define CP_WAIT0()  asm volatile("cp.async.wait_group 0;" ::: "memory")

__device__ __forceinline__ void mma_tf32(float* c, const uint32_t* a, const uint32_t* b) {
    asm volatile(
        "mma.sync.aligned.m16n8k8.row.col.f32.tf32.tf32.f32 "
        "{%0,%1,%2,%3}, {%4,%5,%6,%7}, {%8,%9}, {%0,%1,%2,%3};"
        : "+f"(c[0]), "+f"(c[1]), "+f"(c[2]), "+f"(c[3])
        : "r"(a[0]), "r"(a[1]), "r"(a[2]), "r"(a[3]), "r"(b[0]), "r"(b[1]));
}

// ---------------------------------------------------------------------------
// round_tf32: f32 -> tf32-rounded f32 (RNA), vectorized
// ---------------------------------------------------------------------------
__global__ void round_tf32_kernel(const float* __restrict__ in, float* __restrict__ out, int n4) {
    int i = blockIdx.x * blockDim.x + threadIdx.x;
    if (i >= n4) return;
    float4 v = reinterpret_cast<const float4*>(in)[i];
    v.x = round_tf32v(v.x); v.y = round_tf32v(v.y);
    v.z = round_tf32v(v.z); v.w = round_tf32v(v.w);
    reinterpret_cast<float4*>(out)[i] = v;
}

// ---------------------------------------------------------------------------
// tf32 mma.sync GEMM: C[m,n] = sum_k A[m,k]*B[n,k] + bias[n]
// A:(M,384), B:(N,384) row-major, tf32-pre-rounded. Tile 128x128, BK=32.
// 256 threads = 8 warps (2m x 4n), warp tile 64x32, m16n8k8 atoms.
// ---------------------------------------------------------------------------
#define SROW 36                      // smem row stride (floats): banks (4g+t)%32 distinct
#define STAGEF (128 * SROW)          // floats per matrix per stage

__global__ __launch_bounds__(256, 2)
void gemm_tf32(const float* __restrict__ A, const float* __restrict__ B,
               const float* __restrict__ bias, float* __restrict__ C, int N) {
    extern __shared__ float sm[];
    const int tid  = threadIdx.x;
    const int m0   = blockIdx.y * 128;
    const int n0   = blockIdx.x * 128;
    const int warp = tid >> 5, lane = tid & 31;
    const int wm = warp >> 2, wn = warp & 3;       // 2 x 4 warp grid
    const int g = lane >> 2, t = lane & 3;

    const uint32_t sbase = smem_u32(sm);

    float acc[4][4][4];
#pragma unroll
    for (int mi = 0; mi < 4; mi++)
#pragma unroll
        for (int ni = 0; ni < 4; ni++)
#pragma unroll
            for (int r = 0; r < 4; r++) acc[mi][ni][r] = 0.f;

    const int lm = tid >> 3;          // 0..31? no: tid 0..255 -> m chunk base
    const int lk = tid & 7;

    // async load of stage s into buffer buf
    auto load_stage = [&](int s, int buf) {
        const uint32_t da = sbase + (uint32_t)(buf * 2)     * STAGEF * 4;
        const uint32_t db = sbase + (uint32_t)(buf * 2 + 1) * STAGEF * 4;
#pragma unroll
        for (int i = 0; i < 4; i++) {
            const int m = lm + i * 32;                     // 0..127
            const uint32_t doff = (uint32_t)(m * SROW + lk * 4) * 4;
            CP_ASYNC16(da + doff, A + (size_t)(m0 + m) * KDEPTH + s * 32 + lk * 4);
            CP_ASYNC16(db + doff, B + (size_t)(n0 + m) * KDEPTH + s * 32 + lk * 4);
        }
        CP_COMMIT();
    };

    load_stage(0, 0);

    for (int s = 0; s < NSTG; s++) {
        if (s < NSTG - 1) { load_stage(s + 1, (s + 1) & 1); CP_WAIT1(); }
        else              { CP_WAIT0(); }
        __syncthreads();

        const float* sA = sm + ((s & 1) * 2)     * STAGEF;
        const float* sB = sm + ((s & 1) * 2 + 1) * STAGEF;

#pragma unroll
        for (int kk = 0; kk < 32; kk += 8) {
            uint32_t a[4][4], b[4][2];
#pragma unroll
            for (int mi = 0; mi < 4; mi++) {
                const int r = wm * 64 + mi * 16 + g;
                a[mi][0] = __float_as_uint(sA[r       * SROW + kk + t]);
                a[mi][1] = __float_as_uint(sA[(r + 8) * SROW + kk + t]);
                a[mi][2] = __float_as_uint(sA[r       * SROW + kk + t + 4]);
                a[mi][3] = __float_as_uint(sA[(r + 8) * SROW + kk + t + 4]);
            }
#pragma unroll
            for (int ni = 0; ni < 4; ni++) {
                const int c = wn * 32 + ni * 8 + g;
                b[ni][0] = __float_as_uint(sB[c * SROW + kk + t]);
                b[ni][1] = __float_as_uint(sB[c * SROW + kk + t + 4]);
            }
#pragma unroll
            for (int mi = 0; mi < 4; mi++)
#pragma unroll
                for (int ni = 0; ni < 4; ni++)
                    mma_tf32(acc[mi][ni], a[mi], b[ni]);
        }
        __syncthreads();
    }

    // Epilogue: +bias, float2 stores
#pragma unroll
    for (int mi = 0; mi < 4; mi++) {
        const int row = m0 + wm * 64 + mi * 16 + g;
#pragma unroll
        for (int ni = 0; ni < 4; ni++) {
            const int col = n0 + wn * 32 + ni * 8 + 2 * t;
            const float b0 = bias[col], b1 = bias[col + 1];
            float2 o0 = { acc[mi][ni][0] + b0, acc[mi][ni][1] + b1 };
            float2 o1 = { acc[mi][ni][2] + b0, acc[mi][ni][3] + b1 };
            *reinterpret_cast<float2*>(&C[(size_t)row       * N + col]) = o0;
            *reinterpret_cast<float2*>(&C[(size_t)(row + 8) * N + col]) = o1;
        }
    }
}

// ---------------------------------------------------------------------------
// Attention per (b, h): register-tiled QK^T + softmax + PV.
// 128 threads. Output written tf32-rounded into g_att (proj GEMM input).
// ---------------------------------------------------------------------------
__global__ __launch_bounds__(128)
void attn_kernel(const float* __restrict__ mask, const float* __restrict__ rpb) {
    const int b = blockIdx.x;
    const int h = blockIdx.y;
    const int tid = threadIdx.x;

    __shared__ float qs[64][33];
    __shared__ float ks[64][33];
    __shared__ float vs[64][36];      // 16B-aligned rows for float4 loads
    __shared__ float at[64][67];

    const float scale = 0.17677669529663687f;   // 32^-0.5
    const size_t base = (size_t)b * NTOK * QKVC + (size_t)h * HD;

    for (int idx = tid; idx < NTOK * HD; idx += 128) {
        const int n = idx >> 5, d = idx & 31;
        const size_t r = base + (size_t)n * QKVC + d;
        qs[n][d] = g_qkv[r] * scale;
        ks[n][d] = g_qkv[r + DIMC];
        vs[n][d] = g_qkv[r + 2 * DIMC];
    }
    __syncthreads();

    // ---- QK^T: thread (ty,tx), ty=tid>>3 (i block of 4), tx=tid&7 (j cyclic by 8)
    {
        const int ty = tid >> 3, tx = tid & 7;
        const int i0 = ty * 4;
        float s[4][8];
#pragma unroll
        for (int r = 0; r < 4; r++)
#pragma unroll
            for (int c = 0; c < 8; c++) s[r][c] = 0.f;

#pragma unroll 8
        for (int k = 0; k < HD; k++) {
            float qv[4], kv[8];
#pragma unroll
            for (int r = 0; r < 4; r++) qv[r] = qs[i0 + r][k];
#pragma unroll
            for (int c = 0; c < 8; c++) kv[c] = ks[tx + 8 * c][k];
#pragma unroll
            for (int r = 0; r < 4; r++)
#pragma unroll
                for (int c = 0; c < 8; c++) s[r][c] = fmaf(qv[r], kv[c], s[r][c]);
        }

        const int w = b & 63;
#pragma unroll
        for (int r = 0; r < 4; r++) {
            const int i = i0 + r;
#pragma unroll
            for (int c = 0; c < 8; c++) {
                const int j = tx + 8 * c;
                float v = s[r][c];
                if (i >= NP && i < NTOK && j >= NP && j < NTOK) {
                    const int pi = i - NP, pj = j - NP;
                    const int r1 = pi / 7, c1 = pi - r1 * 7;
                    const int r2 = pj / 7, c2 = pj - r2 * 7;
                    const int ridx = (r1 - r2 + 6) * 13 + (c1 - c2 + 6);
                    v += rpb[ridx * NH + h] + mask[((size_t)w * WINSZ + pi) * WINSZ + pj];
                }
                at[i][j] = v;
            }
        }
    }
    __syncthreads();

    // ---- softmax: warp per row
    {
        const int warp = tid >> 5, lane = tid & 31;
        for (int r = warp; r < NTOK; r += 4) {
            const bool hi = (lane + 32) < NTOK;
            float v0 = at[r][lane];
            float v1 = hi ? at[r][lane + 32] : -1e30f;
            float m = fmaxf(v0, v1);
#pragma unroll
            for (int o = 16; o > 0; o >>= 1)
                m = fmaxf(m, __shfl_xor_sync(0xffffffffu, m, o));
            float e0 = __expf(v0 - m);
            float e1 = hi ? __expf(v1 - m) : 0.f;
            float sum = e0 + e1;
#pragma unroll
            for (int o = 16; o > 0; o >>= 1)
                sum += __shfl_xor_sync(0xffffffffu, sum, o);
            const float inv = 1.f / sum;
            at[r][lane] = e0 * inv;
            if (hi) at[r][lane + 32] = e1 * inv;
        }
    }
    __syncthreads();

    // ---- PV: thread (ty,tx), i block of 4, d block of 4 (float4 on V)
    {
        const int ty = tid >> 3, tx = tid & 7;
        const int i0 = ty * 4, d0 = tx * 4;
        float o[4][4];
#pragma unroll
        for (int r = 0; r < 4; r++)
#pragma unroll
            for (int d = 0; d < 4; d++) o[r][d] = 0.f;

#pragma unroll 6
        for (int j = 0; j < NTOK; j++) {
            const float4 vv = *reinterpret_cast<const float4*>(&vs[j][d0]);
            float av[4];
#pragma unroll
            for (int r = 0; r < 4; r++) av[r] = at[i0 + r][j];
#pragma unroll
            for (int r = 0; r < 4; r++) {
                o[r][0] = fmaf(av[r], vv.x, o[r][0]);
                o[r][1] = fmaf(av[r], vv.y, o[r][1]);
                o[r][2] = fmaf(av[r], vv.z, o[r][2]);
                o[r][3] = fmaf(av[r], vv.w, o[r][3]);
            }
        }
#pragma unroll
        for (int r = 0; r < 4; r++) {
            const int i = i0 + r;
            if (i < NTOK) {
                float4 ov;
                ov.x = round_tf32v(o[r][0]);
                ov.y = round_tf32v(o[r][1]);
                ov.z = round_tf32v(o[r][2]);
                ov.w = round_tf32v(o[r][3]);
                *reinterpret_cast<float4*>(
                    &g_att[((size_t)b * NTOK + i) * DIMC + (size_t)h * HD + d0]) = ov;
            }
        }
    }
}

// ---------------------------------------------------------------------------
extern "C" void kernel_launch(void* const* d_in, const int* in_sizes, int n_in,
                              void* d_out, int out_size) {
    const float* x      = (const float*)d_in[0];
    const float* mask   = (const float*)d_in[1];
    const float* qkv_w  = (const float*)d_in[2];
    const float* qkv_b  = (const float*)d_in[3];
    const float* proj_w = (const float*)d_in[4];
    const float* proj_b = (const float*)d_in[5];
    const float* rpb    = (const float*)d_in[6];
    float* out = (float*)d_out;

    float *xr, *wr, *wr2, *qkvbuf, *attbuf;
    cudaGetSymbolAddress((void**)&xr,     g_xr);
    cudaGetSymbolAddress((void**)&wr,     g_wr);
    cudaGetSymbolAddress((void**)&wr2,    g_wr2);
    cudaGetSymbolAddress((void**)&qkvbuf, g_qkv);
    cudaGetSymbolAddress((void**)&attbuf, g_att);

    const int SMEM_SZ = 4 * STAGEF * 4;   // 73728 B
    cudaFuncSetAttribute(gemm_tf32, cudaFuncAttributeMaxDynamicSharedMemorySize, SMEM_SZ);

    // 1) tf32-RNA rounding prepass
    {
        const int n4x = MROWS * DIMC / 4;
        round_tf32_kernel<<<(n4x + 255) / 256, 256>>>(x, xr, n4x);
        const int n4w = QKVC * DIMC / 4;
        round_tf32_kernel<<<(n4w + 255) / 256, 256>>>(qkv_w, wr, n4w);
        const int n4p = DIMC * DIMC / 4;
        round_tf32_kernel<<<(n4p + 255) / 256, 256>>>(proj_w, wr2, n4p);
    }
    // 2) QKV GEMM: (55296,384)x(1152,384)^T -> g_qkv
    gemm_tf32<<<dim3(QKVC / 128, MROWS / 128), 256, SMEM_SZ>>>(xr, wr, qkv_b, qkvbuf, QKVC);
    // 3) Attention
    attn_kernel<<<dim3(BATCH, NH), 128>>>(mask, rpb);
    // 4) Proj GEMM: (55296,384)x(384,384)^T -> out
    gemm_tf32<<<dim3(DIMC / 128, MROWS / 128), 256, SMEM_SZ>>>(attbuf, wr2, proj_b, out, DIMC);
}